// round 4
// baseline (speedup 1.0000x reference)
#include <cuda_runtime.h>
#include <math.h>
#include <stdint.h>

// ---------------------------------------------------------------------------
// Problem constants
// ---------------------------------------------------------------------------
#define Fdim 128
#define Ndim 512
#define MDL  512
#define HEADS 8
#define Edim 64
#define Mfeat 128
#define HID 256
#define ROWS (Fdim * Ndim)          // 65536
#define QKV_STRIDE (3 * MDL)        // 1536
#define ROW_QKV ((size_t)Ndim * QKV_STRIDE)

#define DN 0.35355339059327373f      // 64^-0.25
#define RATIO 0.08838834764831845f   // 128^-0.5
#define KEPS 1e-4f
#define ZEPS 1e-6f
#define LNEPS 1e-5f

// ---------------------------------------------------------------------------
// Scratch (device globals — no allocation allowed)
// ---------------------------------------------------------------------------
__device__ float g_qkv[(size_t)ROWS * QKV_STRIDE];
__device__ float g_t[(size_t)ROWS * MDL];
__device__ float g_x1[(size_t)ROWS * MDL];
__device__ float g_h1[(size_t)ROWS * HID];

#define MMA_TF32(acc, a0, a1, a2, a3, b0, b1)                                 \
    asm volatile(                                                             \
        "mma.sync.aligned.m16n8k8.row.col.f32.tf32.tf32.f32 "                 \
        "{%0,%1,%2,%3}, {%4,%5,%6,%7}, {%8,%9}, {%0,%1,%2,%3};"               \
        : "+f"(acc[0]), "+f"(acc[1]), "+f"(acc[2]), "+f"(acc[3])              \
        : "r"(a0), "r"(a1), "r"(a2), "r"(a3), "r"(b0), "r"(b1))

__device__ __forceinline__ void cp16(void* smem_dst, const void* gmem_src) {
    unsigned d = (unsigned)__cvta_generic_to_shared(smem_dst);
    asm volatile("cp.async.cg.shared.global [%0], [%1], 16;" :: "r"(d), "l"(gmem_src));
}
__device__ __forceinline__ void cp_commit() {
    asm volatile("cp.async.commit_group;");
}

__device__ __forceinline__ uint32_t fbits(float f) { return __float_as_uint(f); }

// ---------------------------------------------------------------------------
// Pipelined tf32 GEMM: C[M,N] = A[M,K] @ B[N,K]^T + bias[N], optional GELU.
// BM=BN=128, BK=16, 2-stage cp.async. Raw fp32 fed to tf32 MMA (HW truncates).
// ---------------------------------------------------------------------------
__global__ void __launch_bounds__(256) tf32gemm(
    const float* __restrict__ A, const float* __restrict__ B,
    const float* __restrict__ bias, float* __restrict__ C,
    int M, int N, int K, int act)
{
    __shared__ float As[2][128 * 20];
    __shared__ float Bs[2][128 * 20];

    const int tid  = threadIdx.x;
    const int lane = tid & 31;
    const int w    = tid >> 5;
    const int warp_m = w & 1;    // 64 rows
    const int warp_n = w >> 1;   // 32 cols
    const int gid = lane >> 2;
    const int tig = lane & 3;

    const int bm = blockIdx.y, bn = blockIdx.x;
    const float* Ag = A + (size_t)bm * 128 * K;
    const float* Bg = B + (size_t)bn * 128 * K;

    // loader: 512 16B-chunks per tensor per stage; 2 per thread
    const int l_row0 = tid >> 2;                 // slot i=0
    const int l_c0   = (tid & 3) * 4;
    const int l_row1 = (tid + 256) >> 2;         // slot i=1
    const int l_c1   = ((tid + 256) & 3) * 4;

    const int nk = K / 16;

    // prefetch stage 0
    {
        cp16(&As[0][l_row0 * 20 + l_c0], Ag + (size_t)l_row0 * K + l_c0);
        cp16(&As[0][l_row1 * 20 + l_c1], Ag + (size_t)l_row1 * K + l_c1);
        cp16(&Bs[0][l_row0 * 20 + l_c0], Bg + (size_t)l_row0 * K + l_c0);
        cp16(&Bs[0][l_row1 * 20 + l_c1], Bg + (size_t)l_row1 * K + l_c1);
        cp_commit();
    }

    float acc[4][4][4];
#pragma unroll
    for (int mt = 0; mt < 4; ++mt)
#pragma unroll
        for (int nt = 0; nt < 4; ++nt)
#pragma unroll
            for (int r = 0; r < 4; ++r) acc[mt][nt][r] = 0.f;

    for (int c = 0; c < nk; ++c) {
        if (c + 1 < nk) {
            int k0 = (c + 1) * 16;
            int st = (c + 1) & 1;
            cp16(&As[st][l_row0 * 20 + l_c0], Ag + (size_t)l_row0 * K + k0 + l_c0);
            cp16(&As[st][l_row1 * 20 + l_c1], Ag + (size_t)l_row1 * K + k0 + l_c1);
            cp16(&Bs[st][l_row0 * 20 + l_c0], Bg + (size_t)l_row0 * K + k0 + l_c0);
            cp16(&Bs[st][l_row1 * 20 + l_c1], Bg + (size_t)l_row1 * K + k0 + l_c1);
            cp_commit();
            asm volatile("cp.async.wait_group 1;");
        } else {
            asm volatile("cp.async.wait_group 0;");
        }
        __syncthreads();

        const float* as = As[c & 1];
        const float* bs = Bs[c & 1];
#pragma unroll
        for (int kk = 0; kk < 16; kk += 8) {
            uint32_t a[4][4];
#pragma unroll
            for (int mt = 0; mt < 4; ++mt) {
                int ar = warp_m * 64 + mt * 16 + gid;
                a[mt][0] = fbits(as[ar * 20 + kk + tig]);
                a[mt][1] = fbits(as[(ar + 8) * 20 + kk + tig]);
                a[mt][2] = fbits(as[ar * 20 + kk + tig + 4]);
                a[mt][3] = fbits(as[(ar + 8) * 20 + kk + tig + 4]);
            }
#pragma unroll
            for (int nt = 0; nt < 4; ++nt) {
                int br = warp_n * 32 + nt * 8 + gid;
                uint32_t b0 = fbits(bs[br * 20 + kk + tig]);
                uint32_t b1 = fbits(bs[br * 20 + kk + tig + 4]);
#pragma unroll
                for (int mt = 0; mt < 4; ++mt)
                    MMA_TF32(acc[mt][nt], a[mt][0], a[mt][1], a[mt][2], a[mt][3], b0, b1);
            }
        }
        __syncthreads();
    }

    // Epilogue: bias + optional exact GELU
#pragma unroll
    for (int mt = 0; mt < 4; ++mt) {
        int row = bm * 128 + warp_m * 64 + mt * 16 + gid;
#pragma unroll
        for (int nt = 0; nt < 4; ++nt) {
            int col = bn * 128 + warp_n * 32 + nt * 8 + 2 * tig;
            float b0 = bias[col], b1 = bias[col + 1];
            float v0 = acc[mt][nt][0] + b0;
            float v1 = acc[mt][nt][1] + b1;
            float v2 = acc[mt][nt][2] + b0;
            float v3 = acc[mt][nt][3] + b1;
            if (act) {
                v0 = 0.5f * v0 * (1.0f + erff(v0 * 0.7071067811865476f));
                v1 = 0.5f * v1 * (1.0f + erff(v1 * 0.7071067811865476f));
                v2 = 0.5f * v2 * (1.0f + erff(v2 * 0.7071067811865476f));
                v3 = 0.5f * v3 * (1.0f + erff(v3 * 0.7071067811865476f));
            }
            *(float2*)(C + (size_t)row * N + col)       = make_float2(v0, v1);
            *(float2*)(C + (size_t)(row + 8) * N + col) = make_float2(v2, v3);
        }
    }
}

// ---------------------------------------------------------------------------
// Fused FAVOR+ attention per (n,h) block (raw fp32 into tf32 MMA).
// Shared memory (word offsets):
//   QF [128][132]  0       (later P)
//   KF [128][132]  16896
//   DB [128][68]   33792   (q/k tile; later vT [64][132])
//   PB [128][68]   42496   (proj)
//   DS [128]       51200
//   DEN[128]       51328
// ---------------------------------------------------------------------------
__global__ void __launch_bounds__(256) fused_attn(const float* __restrict__ proj)
{
    extern __shared__ uint32_t smw[];
    uint32_t* QF = smw;
    uint32_t* KF = smw + 16896;
    uint32_t* DB = smw + 33792;
    uint32_t* PB = smw + 42496;
    float* DS  = (float*)(smw + 51200);
    float* DEN = (float*)(smw + 51328);

    const int bx = blockIdx.x;
    const int n = bx >> 3, h = bx & 7;
    const int tid  = threadIdx.x;
    const int lane = tid & 31, w = tid >> 5;
    const int gid = lane >> 2, tig = lane & 3;
    const int r0 = w * 16 + gid, r1 = r0 + 8;

    const size_t base_nh = (size_t)n * QKV_STRIDE + (size_t)h * Edim;

    // ---- load proj -> PB ----
    {
        int m = tid >> 1, e0 = (tid & 1) * 32;
        const float* src = proj + m * 64 + e0;
#pragma unroll
        for (int j = 0; j < 8; ++j) {
            float4 v = *(const float4*)(src + j * 4);
            int o = m * 68 + e0 + j * 4;
            PB[o + 0] = fbits(v.x); PB[o + 1] = fbits(v.y);
            PB[o + 2] = fbits(v.z); PB[o + 3] = fbits(v.w);
        }
    }

    // ---- feature maps for q (sel=0) and k (sel=1) ----
    for (int sel = 0; sel < 2; ++sel) {
        {
            int r = tid >> 1, e0 = (tid & 1) * 32;
            const float* src = g_qkv + (size_t)r * ROW_QKV + base_nh
                               + (size_t)sel * MDL + e0;
            float sq = 0.f;
#pragma unroll
            for (int j = 0; j < 8; ++j) {
                float4 v = *(const float4*)(src + j * 4);
                sq += v.x * v.x + v.y * v.y + v.z * v.z + v.w * v.w;
                int o = r * 68 + e0 + j * 4;
                DB[o + 0] = fbits(v.x); DB[o + 1] = fbits(v.y);
                DB[o + 2] = fbits(v.z); DB[o + 3] = fbits(v.w);
            }
            sq += __shfl_xor_sync(0xffffffffu, sq, 1);
            if ((tid & 1) == 0) DS[r] = sq;
        }
        __syncthreads();

        float acc[16][4];
#pragma unroll
        for (int nt = 0; nt < 16; ++nt)
#pragma unroll
            for (int r = 0; r < 4; ++r) acc[nt][r] = 0.f;

#pragma unroll
        for (int kk = 0; kk < 64; kk += 8) {
            uint32_t a0 = DB[r0 * 68 + kk + tig];
            uint32_t a1 = DB[r1 * 68 + kk + tig];
            uint32_t a2 = DB[r0 * 68 + kk + tig + 4];
            uint32_t a3 = DB[r1 * 68 + kk + tig + 4];
#pragma unroll
            for (int nt = 0; nt < 16; ++nt) {
                uint32_t b0 = PB[(nt * 8 + gid) * 68 + kk + tig];
                uint32_t b1 = PB[(nt * 8 + gid) * 68 + kk + tig + 4];
                MMA_TF32(acc[nt], a0, a1, a2, a3, b0, b1);
            }
        }

        float m0 = -1e30f, m1 = -1e30f;
#pragma unroll
        for (int nt = 0; nt < 16; ++nt) {
            m0 = fmaxf(m0, fmaxf(acc[nt][0], acc[nt][1]));
            m1 = fmaxf(m1, fmaxf(acc[nt][2], acc[nt][3]));
        }
        m0 = fmaxf(m0, __shfl_xor_sync(0xffffffffu, m0, 1));
        m0 = fmaxf(m0, __shfl_xor_sync(0xffffffffu, m0, 2));
        m1 = fmaxf(m1, __shfl_xor_sync(0xffffffffu, m1, 1));
        m1 = fmaxf(m1, __shfl_xor_sync(0xffffffffu, m1, 2));

        float c0 = -DS[r0] * (0.5f * DN * DN) - m0 * DN;
        float c1 = -DS[r1] * (0.5f * DN * DN) - m1 * DN;

        uint32_t* OUT = sel ? KF : QF;
#pragma unroll
        for (int nt = 0; nt < 16; ++nt) {
            int col = nt * 8 + 2 * tig;
            OUT[r0 * 132 + col]     = fbits(RATIO * (expf(acc[nt][0] * DN + c0) + KEPS));
            OUT[r0 * 132 + col + 1] = fbits(RATIO * (expf(acc[nt][1] * DN + c0) + KEPS));
            OUT[r1 * 132 + col]     = fbits(RATIO * (expf(acc[nt][2] * DN + c1) + KEPS));
            OUT[r1 * 132 + col + 1] = fbits(RATIO * (expf(acc[nt][3] * DN + c1) + KEPS));
        }
        __syncthreads();
    }

    // ---- load v -> DB as vT[e][s] ----
    {
        int s = tid >> 1, e0 = (tid & 1) * 32;
        const float* src = g_qkv + (size_t)s * ROW_QKV + base_nh + 2 * MDL + e0;
#pragma unroll
        for (int j = 0; j < 8; ++j) {
            float4 v = *(const float4*)(src + j * 4);
            DB[(e0 + j * 4 + 0) * 132 + s] = fbits(v.x);
            DB[(e0 + j * 4 + 1) * 132 + s] = fbits(v.y);
            DB[(e0 + j * 4 + 2) * 132 + s] = fbits(v.z);
            DB[(e0 + j * 4 + 3) * 132 + s] = fbits(v.w);
        }
    }

    // ---- P = qf @ kf^T ----
    float acc[16][4];
#pragma unroll
    for (int nt = 0; nt < 16; ++nt)
#pragma unroll
        for (int r = 0; r < 4; ++r) acc[nt][r] = 0.f;

#pragma unroll
    for (int kk = 0; kk < 128; kk += 8) {
        uint32_t a0 = QF[r0 * 132 + kk + tig];
        uint32_t a1 = QF[r1 * 132 + kk + tig];
        uint32_t a2 = QF[r0 * 132 + kk + tig + 4];
        uint32_t a3 = QF[r1 * 132 + kk + tig + 4];
#pragma unroll
        for (int nt = 0; nt < 16; ++nt) {
            uint32_t b0 = KF[(nt * 8 + gid) * 132 + kk + tig];
            uint32_t b1 = KF[(nt * 8 + gid) * 132 + kk + tig + 4];
            MMA_TF32(acc[nt], a0, a1, a2, a3, b0, b1);
        }
    }

    {
        float d0 = 0.f, d1 = 0.f;
#pragma unroll
        for (int nt = 0; nt < 16; ++nt) {
            d0 += acc[nt][0] + acc[nt][1];
            d1 += acc[nt][2] + acc[nt][3];
        }
        d0 += __shfl_xor_sync(0xffffffffu, d0, 1);
        d0 += __shfl_xor_sync(0xffffffffu, d0, 2);
        d1 += __shfl_xor_sync(0xffffffffu, d1, 1);
        d1 += __shfl_xor_sync(0xffffffffu, d1, 2);
        if (tig == 0) { DEN[r0] = d0; DEN[r1] = d1; }
    }
    __syncthreads();

#pragma unroll
    for (int nt = 0; nt < 16; ++nt) {
        int col = nt * 8 + 2 * tig;
        QF[r0 * 132 + col]     = fbits(acc[nt][0]);
        QF[r0 * 132 + col + 1] = fbits(acc[nt][1]);
        QF[r1 * 132 + col]     = fbits(acc[nt][2]);
        QF[r1 * 132 + col + 1] = fbits(acc[nt][3]);
    }
    __syncthreads();

    // ---- t = (P @ v) / den ----
    float acc3[8][4];
#pragma unroll
    for (int nt = 0; nt < 8; ++nt)
#pragma unroll
        for (int r = 0; r < 4; ++r) acc3[nt][r] = 0.f;

#pragma unroll
    for (int kk = 0; kk < 128; kk += 8) {
        uint32_t a0 = QF[r0 * 132 + kk + tig];
        uint32_t a1 = QF[r1 * 132 + kk + tig];
        uint32_t a2 = QF[r0 * 132 + kk + tig + 4];
        uint32_t a3 = QF[r1 * 132 + kk + tig + 4];
#pragma unroll
        for (int nt = 0; nt < 8; ++nt) {
            uint32_t b0 = DB[(nt * 8 + gid) * 132 + kk + tig];
            uint32_t b1 = DB[(nt * 8 + gid) * 132 + kk + tig + 4];
            MMA_TF32(acc3[nt], a0, a1, a2, a3, b0, b1);
        }
    }

    const float inv0 = 1.0f / (DEN[r0] + ZEPS);
    const float inv1 = 1.0f / (DEN[r1] + ZEPS);
#pragma unroll
    for (int nt = 0; nt < 8; ++nt) {
        int col = nt * 8 + 2 * tig;
        *(float2*)&g_t[((size_t)r0 * Ndim + n) * MDL + h * Edim + col] =
            make_float2(acc3[nt][0] * inv0, acc3[nt][1] * inv0);
        *(float2*)&g_t[((size_t)r1 * Ndim + n) * MDL + h * Edim + col] =
            make_float2(acc3[nt][2] * inv1, acc3[nt][3] * inv1);
    }
}

// ---------------------------------------------------------------------------
// FFN2 + final AddNorm fused:
//   y = A @ w2^T + b2;  out = LN(y + x1) * g + b
// Block: 64 rows x 512 cols (full N), K=256. 8 warps, warp tile 32x128.
// Smem words: As[64][36]=2304, Bs[512][36]=18432, redS[64][4], redS2[64][4]
// ---------------------------------------------------------------------------
__global__ void __launch_bounds__(256) ffn2_ln(
    const float* __restrict__ A, const float* __restrict__ B,
    const float* __restrict__ bias, const float* __restrict__ resid,
    const float* __restrict__ gamma, const float* __restrict__ beta,
    float* __restrict__ out)
{
    extern __shared__ float sm[];
    float* As = sm;                       // [64][36]
    float* Bs = sm + 64 * 36;             // [512][36]
    float* redS  = sm + 64 * 36 + 512 * 36;
    float* redS2 = redS + 64 * 4;

    const int tid  = threadIdx.x;
    const int lane = tid & 31, w = tid >> 5;
    const int gid = lane >> 2, tig = lane & 3;
    const int warp_m = w & 1, warp_n = w >> 1;
    const int row0 = blockIdx.x * 64;

    float acc[2][16][4];
#pragma unroll
    for (int mt = 0; mt < 2; ++mt)
#pragma unroll
        for (int nt = 0; nt < 16; ++nt)
#pragma unroll
            for (int r = 0; r < 4; ++r) acc[mt][nt][r] = 0.f;

    for (int k0 = 0; k0 < 256; k0 += 32) {
#pragma unroll
        for (int i = 0; i < 2; ++i) {
            int slot = tid + i * 256;
            int r = slot >> 3, c4 = (slot & 7) * 4;
            *(float4*)&As[r * 36 + c4] =
                *(const float4*)&A[(size_t)(row0 + r) * HID + k0 + c4];
        }
#pragma unroll
        for (int i = 0; i < 16; ++i) {
            int slot = tid + i * 256;
            int r = slot >> 3, c4 = (slot & 7) * 4;
            *(float4*)&Bs[r * 36 + c4] =
                *(const float4*)&B[(size_t)r * HID + k0 + c4];
        }
        __syncthreads();

#pragma unroll
        for (int kk = 0; kk < 32; kk += 8) {
            uint32_t a[2][4];
#pragma unroll
            for (int mt = 0; mt < 2; ++mt) {
                int ar = warp_m * 32 + mt * 16 + gid;
                a[mt][0] = fbits(As[ar * 36 + kk + tig]);
                a[mt][1] = fbits(As[(ar + 8) * 36 + kk + tig]);
                a[mt][2] = fbits(As[ar * 36 + kk + tig + 4]);
                a[mt][3] = fbits(As[(ar + 8) * 36 + kk + tig + 4]);
            }
#pragma unroll
            for (int nt = 0; nt < 16; ++nt) {
                int bc = warp_n * 128 + nt * 8 + gid;
                uint32_t b0 = fbits(Bs[bc * 36 + kk + tig]);
                uint32_t b1 = fbits(Bs[bc * 36 + kk + tig + 4]);
                MMA_TF32(acc[0][nt], a[0][0], a[0][1], a[0][2], a[0][3], b0, b1);
                MMA_TF32(acc[1][nt], a[1][0], a[1][1], a[1][2], a[1][3], b0, b1);
            }
        }
        __syncthreads();
    }

    // epilogue: add bias + residual, row sums for LN
#pragma unroll
    for (int mt = 0; mt < 2; ++mt) {
        int lrA = warp_m * 32 + mt * 16 + gid;
        int lrB = lrA + 8;
        int rA = row0 + lrA, rB = row0 + lrB;
        float sA = 0.f, qA = 0.f, sB = 0.f, qB = 0.f;
#pragma unroll
        for (int nt = 0; nt < 16; ++nt) {
            int col = warp_n * 128 + nt * 8 + 2 * tig;
            float b0 = bias[col], b1 = bias[col + 1];
            float2 xA = *(const float2*)&resid[(size_t)rA * MDL + col];
            float2 xB = *(const float2*)&resid[(size_t)rB * MDL + col];
            float v0 = acc[mt][nt][0] + b0 + xA.x;
            float v1 = acc[mt][nt][1] + b1 + xA.y;
            float v2 = acc[mt][nt][2] + b0 + xB.x;
            float v3 = acc[mt][nt][3] + b1 + xB.y;
            acc[mt][nt][0] = v0; acc[mt][nt][1] = v1;
            acc[mt][nt][2] = v2; acc[mt][nt][3] = v3;
            sA += v0 + v1; qA += v0 * v0 + v1 * v1;
            sB += v2 + v3; qB += v2 * v2 + v3 * v3;
        }
#pragma unroll
        for (int o = 1; o < 4; o <<= 1) {
            sA += __shfl_xor_sync(0xffffffffu, sA, o);
            qA += __shfl_xor_sync(0xffffffffu, qA, o);
            sB += __shfl_xor_sync(0xffffffffu, sB, o);
            qB += __shfl_xor_sync(0xffffffffu, qB, o);
        }
        if (tig == 0) {
            redS[lrA * 4 + warp_n]  = sA;  redS2[lrA * 4 + warp_n] = qA;
            redS[lrB * 4 + warp_n]  = sB;  redS2[lrB * 4 + warp_n] = qB;
        }
    }
    __syncthreads();

#pragma unroll
    for (int mt = 0; mt < 2; ++mt) {
        int lrA = warp_m * 32 + mt * 16 + gid;
        int lrB = lrA + 8;
        int rA = row0 + lrA, rB = row0 + lrB;
        float tsA = redS[lrA*4] + redS[lrA*4+1] + redS[lrA*4+2] + redS[lrA*4+3];
        float tqA = redS2[lrA*4] + redS2[lrA*4+1] + redS2[lrA*4+2] + redS2[lrA*4+3];
        float tsB = redS[lrB*4] + redS[lrB*4+1] + redS[lrB*4+2] + redS[lrB*4+3];
        float tqB = redS2[lrB*4] + redS2[lrB*4+1] + redS2[lrB*4+2] + redS2[lrB*4+3];
        float mA = tsA * (1.0f / MDL);
        float vA = tqA * (1.0f / MDL) - mA * mA;
        float rsA = rsqrtf(vA + LNEPS);
        float mB = tsB * (1.0f / MDL);
        float vB = tqB * (1.0f / MDL) - mB * mB;
        float rsB = rsqrtf(vB + LNEPS);
#pragma unroll
        for (int nt = 0; nt < 16; ++nt) {
            int col = warp_n * 128 + nt * 8 + 2 * tig;
            float g0 = gamma[col], g1 = gamma[col + 1];
            float be0 = beta[col], be1 = beta[col + 1];
            *(float2*)&out[(size_t)rA * MDL + col] = make_float2(
                (acc[mt][nt][0] - mA) * rsA * g0 + be0,
                (acc[mt][nt][1] - mA) * rsA * g1 + be1);
            *(float2*)&out[(size_t)rB * MDL + col] = make_float2(
                (acc[mt][nt][2] - mB) * rsB * g0 + be0,
                (acc[mt][nt][3] - mB) * rsB * g1 + be1);
        }
    }
}

// ---------------------------------------------------------------------------
// AddNorm (LN1)
// ---------------------------------------------------------------------------
__global__ void __launch_bounds__(128) addnorm_k(
    const float* __restrict__ a, const float* __restrict__ res,
    const float* __restrict__ g, const float* __restrict__ b,
    float* __restrict__ out)
{
    __shared__ float red[8];
    const int r = blockIdx.x, tid = threadIdx.x;
    const size_t base = (size_t)r * MDL + tid * 4;

    float4 va = *(const float4*)(a + base);
    float4 vr = *(const float4*)(res + base);
    float v[4] = { va.x + vr.x, va.y + vr.y, va.z + vr.z, va.w + vr.w };

    float s  = v[0] + v[1] + v[2] + v[3];
    float s2 = v[0]*v[0] + v[1]*v[1] + v[2]*v[2] + v[3]*v[3];
#pragma unroll
    for (int o = 16; o > 0; o >>= 1) {
        s  += __shfl_xor_sync(0xffffffffu, s,  o);
        s2 += __shfl_xor_sync(0xffffffffu, s2, o);
    }
    if ((tid & 31) == 0) { red[tid >> 5] = s; red[4 + (tid >> 5)] = s2; }
    __syncthreads();
    float ts  = red[0] + red[1] + red[2] + red[3];
    float ts2 = red[4] + red[5] + red[6] + red[7];
    float mean = ts * (1.0f / MDL);
    float var  = ts2 * (1.0f / MDL) - mean * mean;
    float rstd = rsqrtf(var + LNEPS);

    float4 gg = *(const float4*)(g + tid * 4);
    float4 bb = *(const float4*)(b + tid * 4);
    float4 o;
    o.x = (v[0] - mean) * rstd * gg.x + bb.x;
    o.y = (v[1] - mean) * rstd * gg.y + bb.y;
    o.z = (v[2] - mean) * rstd * gg.z + bb.z;
    o.w = (v[3] - mean) * rstd * gg.w + bb.w;
    *(float4*)(out + base) = o;
}

// ---------------------------------------------------------------------------
// Host launcher
// ---------------------------------------------------------------------------
extern "C" void kernel_launch(void* const* d_in, const int* in_sizes, int n_in,
                              void* d_out, int out_size)
{
    const float* x     = (const float*)d_in[0];
    const float* w_qkv = (const float*)d_in[1];
    const float* b_qkv = (const float*)d_in[2];
    const float* proj  = (const float*)d_in[3];
    const float* ln1_g = (const float*)d_in[4];
    const float* ln1_b = (const float*)d_in[5];
    const float* ln2_g = (const float*)d_in[6];
    const float* ln2_b = (const float*)d_in[7];
    const float* w1    = (const float*)d_in[8];
    const float* b1    = (const float*)d_in[9];
    const float* w2    = (const float*)d_in[10];
    const float* b2    = (const float*)d_in[11];
    float* out = (float*)d_out;

    float *p_qkv, *p_t, *p_x1, *p_h1;
    cudaGetSymbolAddress((void**)&p_qkv, g_qkv);
    cudaGetSymbolAddress((void**)&p_t,   g_t);
    cudaGetSymbolAddress((void**)&p_x1,  g_x1);
    cudaGetSymbolAddress((void**)&p_h1,  g_h1);

    const int fused_smem = 51456 * 4;                      // 205824 B
    const int ffn2_smem  = (64*36 + 512*36 + 64*8) * 4;    // 84992 B
    cudaFuncSetAttribute(fused_attn, cudaFuncAttributeMaxDynamicSharedMemorySize,
                         fused_smem);
    cudaFuncSetAttribute(ffn2_ln, cudaFuncAttributeMaxDynamicSharedMemorySize,
                         ffn2_smem);

    // 1) qkv = x @ w_qkv^T + b_qkv   [65536, 1536]
    tf32gemm<<<dim3(QKV_STRIDE / 128, ROWS / 128), 256>>>(
        x, w_qkv, b_qkv, p_qkv, ROWS, QKV_STRIDE, MDL, 0);

    // 2) fused FAVOR+ attention -> g_t
    fused_attn<<<Ndim * HEADS, 256, fused_smem>>>(proj);

    // 3) x1 = LN(t + x)
    addnorm_k<<<ROWS, 128>>>(p_t, x, ln1_g, ln1_b, p_x1);

    // 4) h1 = gelu(x1 @ w1^T + b1)   [65536, 256]
    tf32gemm<<<dim3(HID / 128, ROWS / 128), 256>>>(
        p_x1, w1, b1, p_h1, ROWS, HID, MDL, 1);

    // 5) out = LN(h1 @ w2^T + b2 + x1)  (fused FFN2 + AddNorm)
    ffn2_ln<<<ROWS / 64, 256, ffn2_smem>>>(
        p_h1, w2, b2, p_x1, ln2_g, ln2_b, out);
}

// round 5
// speedup vs baseline: 1.2029x; 1.2029x over previous
#include <cuda_runtime.h>
#include <math.h>
#include <stdint.h>

// ---------------------------------------------------------------------------
// Problem constants
// ---------------------------------------------------------------------------
#define Fdim 128
#define Ndim 512
#define MDL  512
#define HEADS 8
#define Edim 64
#define Mfeat 128
#define HID 256
#define ROWS (Fdim * Ndim)          // 65536
#define QKV_STRIDE (3 * MDL)        // 1536
#define ROW_QKV ((size_t)Ndim * QKV_STRIDE)

#define DN 0.35355339059327373f      // 64^-0.25
#define RATIO 0.08838834764831845f   // 128^-0.5
#define KEPS 1e-4f
#define ZEPS 1e-6f
#define LNEPS 1e-5f

// ---------------------------------------------------------------------------
// Scratch (device globals — no allocation allowed)
// ---------------------------------------------------------------------------
__device__ float g_qkv[(size_t)ROWS * QKV_STRIDE];
__device__ float g_t[(size_t)ROWS * MDL];
__device__ float g_x1[(size_t)ROWS * MDL];
__device__ float g_h1[(size_t)ROWS * HID];
__device__ float g_y[(size_t)ROWS * MDL];

#define MMA_TF32(acc, a0, a1, a2, a3, b0, b1)                                 \
    asm volatile(                                                             \
        "mma.sync.aligned.m16n8k8.row.col.f32.tf32.tf32.f32 "                 \
        "{%0,%1,%2,%3}, {%4,%5,%6,%7}, {%8,%9}, {%0,%1,%2,%3};"               \
        : "+f"(acc[0]), "+f"(acc[1]), "+f"(acc[2]), "+f"(acc[3])              \
        : "r"(a0), "r"(a1), "r"(a2), "r"(a3), "r"(b0), "r"(b1))

__device__ __forceinline__ void cp16(void* smem_dst, const void* gmem_src) {
    unsigned d = (unsigned)__cvta_generic_to_shared(smem_dst);
    asm volatile("cp.async.cg.shared.global [%0], [%1], 16;" :: "r"(d), "l"(gmem_src));
}
__device__ __forceinline__ void cp_commit() {
    asm volatile("cp.async.commit_group;");
}
__device__ __forceinline__ uint32_t s2u(const void* p) {
    return (uint32_t)__cvta_generic_to_shared(p);
}
__device__ __forceinline__ void ldm_x4(uint32_t& r0, uint32_t& r1,
                                       uint32_t& r2, uint32_t& r3, uint32_t addr) {
    asm volatile("ldmatrix.sync.aligned.m8n8.x4.shared.b16 {%0,%1,%2,%3}, [%4];"
                 : "=r"(r0), "=r"(r1), "=r"(r2), "=r"(r3) : "r"(addr));
}
__device__ __forceinline__ uint32_t fbits(float f) { return __float_as_uint(f); }

// ---------------------------------------------------------------------------
// Pipelined tf32 GEMM: C[M,N] = A[M,K] @ B[N,K]^T + bias[N], optional GELU.
// BM=BN=128, BK=32, 2-stage cp.async, ldmatrix fragment loads.
// Dynamic smem: A0 A1 B0 B1, each 128x36 floats -> 73728 B.
// ---------------------------------------------------------------------------
__global__ void __launch_bounds__(256) tf32gemm(
    const float* __restrict__ A, const float* __restrict__ B,
    const float* __restrict__ bias, float* __restrict__ C,
    int M, int N, int K, int act)
{
    extern __shared__ float sm[];
    // layout: A stage0 [0,4608), A stage1 [4608,9216), B0 [9216,13824), B1 [13824,18432)

    const int tid  = threadIdx.x;
    const int lane = tid & 31;
    const int w    = tid >> 5;
    const int warp_m = w & 1;    // 64 rows
    const int warp_n = w >> 1;   // 32 cols
    const int gid = lane >> 2;
    const int tig = lane & 3;

    const int bm = blockIdx.y, bn = blockIdx.x;
    const float* Ag = A + (size_t)bm * 128 * K;
    const float* Bg = B + (size_t)bn * 128 * K;

    const int nk = K / 32;

    // ldmatrix per-lane offsets
    const int a_loff = ((lane & 15) * 36 + ((lane >> 4) << 2)) << 2;
    const int b_loff = ((((lane >> 4) << 3) + (lane & 7)) * 36 + (((lane >> 3) & 1) << 2)) << 2;

#define LOAD_STAGE(st, k0)                                                     \
    {                                                                          \
        float* as_ = sm + (st) * 4608;                                         \
        float* bs_ = sm + 9216 + (st) * 4608;                                  \
        _Pragma("unroll")                                                      \
        for (int i = 0; i < 4; ++i) {                                          \
            int slot = tid + i * 256;                                          \
            int r = slot >> 3, c4 = (slot & 7) * 4;                            \
            cp16(&as_[r * 36 + c4], Ag + (size_t)r * K + (k0) + c4);           \
            cp16(&bs_[r * 36 + c4], Bg + (size_t)r * K + (k0) + c4);           \
        }                                                                      \
        cp_commit();                                                           \
    }

    LOAD_STAGE(0, 0)

    float acc[4][4][4];
#pragma unroll
    for (int mt = 0; mt < 4; ++mt)
#pragma unroll
        for (int nt = 0; nt < 4; ++nt)
#pragma unroll
            for (int r = 0; r < 4; ++r) acc[mt][nt][r] = 0.f;

    for (int c = 0; c < nk; ++c) {
        if (c + 1 < nk) {
            LOAD_STAGE((c + 1) & 1, (c + 1) * 32)
            asm volatile("cp.async.wait_group 1;");
        } else {
            asm volatile("cp.async.wait_group 0;");
        }
        __syncthreads();

        const float* as = sm + (c & 1) * 4608;
        const float* bs = sm + 9216 + (c & 1) * 4608;
        uint32_t aB = s2u(as) + ((warp_m * 64 * 36) << 2) + a_loff;
        uint32_t bB = s2u(bs) + ((warp_n * 32 * 36) << 2) + b_loff;

#pragma unroll
        for (int kk = 0; kk < 32; kk += 8) {
            uint32_t a[4][4];
#pragma unroll
            for (int mt = 0; mt < 4; ++mt)
                ldm_x4(a[mt][0], a[mt][1], a[mt][2], a[mt][3],
                       aB + ((mt * 16 * 36 + kk) << 2));
#pragma unroll
            for (int p = 0; p < 2; ++p) {
                uint32_t b0, b1, b2, b3;
                ldm_x4(b0, b1, b2, b3, bB + ((p * 16 * 36 + kk) << 2));
#pragma unroll
                for (int mt = 0; mt < 4; ++mt) {
                    MMA_TF32(acc[mt][2 * p],     a[mt][0], a[mt][1], a[mt][2], a[mt][3], b0, b1);
                    MMA_TF32(acc[mt][2 * p + 1], a[mt][0], a[mt][1], a[mt][2], a[mt][3], b2, b3);
                }
            }
        }
        __syncthreads();
    }
#undef LOAD_STAGE

    // Epilogue: bias + optional exact GELU
#pragma unroll
    for (int mt = 0; mt < 4; ++mt) {
        int row = bm * 128 + warp_m * 64 + mt * 16 + gid;
#pragma unroll
        for (int nt = 0; nt < 4; ++nt) {
            int col = bn * 128 + warp_n * 32 + nt * 8 + 2 * tig;
            float b0 = bias[col], b1 = bias[col + 1];
            float v0 = acc[mt][nt][0] + b0;
            float v1 = acc[mt][nt][1] + b1;
            float v2 = acc[mt][nt][2] + b0;
            float v3 = acc[mt][nt][3] + b1;
            if (act) {
                v0 = 0.5f * v0 * (1.0f + erff(v0 * 0.7071067811865476f));
                v1 = 0.5f * v1 * (1.0f + erff(v1 * 0.7071067811865476f));
                v2 = 0.5f * v2 * (1.0f + erff(v2 * 0.7071067811865476f));
                v3 = 0.5f * v3 * (1.0f + erff(v3 * 0.7071067811865476f));
            }
            *(float2*)(C + (size_t)row * N + col)       = make_float2(v0, v1);
            *(float2*)(C + (size_t)(row + 8) * N + col) = make_float2(v2, v3);
        }
    }
}

// ---------------------------------------------------------------------------
// Fused FAVOR+ attention per (n,h) block, ldmatrix fragment loads.
// Shared memory (word offsets):
//   QF [128][132]  0       (later P)
//   KF [128][132]  16896
//   DB [128][68]   33792   (q/k tile; later vT [64][132])
//   PB [128][68]   42496   (proj)
//   DS [128]       51200
//   DEN[128]       51328
// ---------------------------------------------------------------------------
__global__ void __launch_bounds__(256) fused_attn(const float* __restrict__ proj)
{
    extern __shared__ uint32_t smw[];
    uint32_t* QF = smw;
    uint32_t* KF = smw + 16896;
    uint32_t* DB = smw + 33792;
    uint32_t* PB = smw + 42496;
    float* DS  = (float*)(smw + 51200);
    float* DEN = (float*)(smw + 51328);

    const int bx = blockIdx.x;
    const int n = bx >> 3, h = bx & 7;
    const int tid  = threadIdx.x;
    const int lane = tid & 31, w = tid >> 5;
    const int gid = lane >> 2, tig = lane & 3;
    const int r0 = w * 16 + gid, r1 = r0 + 8;

    // ldmatrix per-lane offsets (in bytes), for strides 68 and 132
    const int a68  = ((lane & 15) * 68  + ((lane >> 4) << 2)) << 2;
    const int a132 = ((lane & 15) * 132 + ((lane >> 4) << 2)) << 2;
    const int b68  = ((((lane >> 4) << 3) + (lane & 7)) * 68  + (((lane >> 3) & 1) << 2)) << 2;
    const int b132 = ((((lane >> 4) << 3) + (lane & 7)) * 132 + (((lane >> 3) & 1) << 2)) << 2;

    const size_t base_nh = (size_t)n * QKV_STRIDE + (size_t)h * Edim;

    // ---- load proj -> PB ----
    {
        int m = tid >> 1, e0 = (tid & 1) * 32;
        const float* src = proj + m * 64 + e0;
#pragma unroll
        for (int j = 0; j < 8; ++j) {
            float4 v = *(const float4*)(src + j * 4);
            int o = m * 68 + e0 + j * 4;
            PB[o + 0] = fbits(v.x); PB[o + 1] = fbits(v.y);
            PB[o + 2] = fbits(v.z); PB[o + 3] = fbits(v.w);
        }
    }

    // ---- feature maps for q (sel=0) and k (sel=1) ----
    for (int sel = 0; sel < 2; ++sel) {
        {
            int r = tid >> 1, e0 = (tid & 1) * 32;
            const float* src = g_qkv + (size_t)r * ROW_QKV + base_nh
                               + (size_t)sel * MDL + e0;
            float sq = 0.f;
#pragma unroll
            for (int j = 0; j < 8; ++j) {
                float4 v = *(const float4*)(src + j * 4);
                sq += v.x * v.x + v.y * v.y + v.z * v.z + v.w * v.w;
                int o = r * 68 + e0 + j * 4;
                DB[o + 0] = fbits(v.x); DB[o + 1] = fbits(v.y);
                DB[o + 2] = fbits(v.z); DB[o + 3] = fbits(v.w);
            }
            sq += __shfl_xor_sync(0xffffffffu, sq, 1);
            if ((tid & 1) == 0) DS[r] = sq;
        }
        __syncthreads();

        float acc[16][4];
#pragma unroll
        for (int nt = 0; nt < 16; ++nt)
#pragma unroll
            for (int r = 0; r < 4; ++r) acc[nt][r] = 0.f;

        {
            uint32_t aB = s2u(DB) + ((w * 16 * 68) << 2) + a68;
            uint32_t bB = s2u(PB) + b68;
#pragma unroll
            for (int kk = 0; kk < 64; kk += 8) {
                uint32_t a0, a1, a2, a3;
                ldm_x4(a0, a1, a2, a3, aB + (kk << 2));
#pragma unroll
                for (int p = 0; p < 8; ++p) {
                    uint32_t b0, b1, b2, b3;
                    ldm_x4(b0, b1, b2, b3, bB + ((p * 16 * 68 + kk) << 2));
                    MMA_TF32(acc[2 * p],     a0, a1, a2, a3, b0, b1);
                    MMA_TF32(acc[2 * p + 1], a0, a1, a2, a3, b2, b3);
                }
            }
        }

        float m0 = -1e30f, m1 = -1e30f;
#pragma unroll
        for (int nt = 0; nt < 16; ++nt) {
            m0 = fmaxf(m0, fmaxf(acc[nt][0], acc[nt][1]));
            m1 = fmaxf(m1, fmaxf(acc[nt][2], acc[nt][3]));
        }
        m0 = fmaxf(m0, __shfl_xor_sync(0xffffffffu, m0, 1));
        m0 = fmaxf(m0, __shfl_xor_sync(0xffffffffu, m0, 2));
        m1 = fmaxf(m1, __shfl_xor_sync(0xffffffffu, m1, 1));
        m1 = fmaxf(m1, __shfl_xor_sync(0xffffffffu, m1, 2));

        float c0 = -DS[r0] * (0.5f * DN * DN) - m0 * DN;
        float c1 = -DS[r1] * (0.5f * DN * DN) - m1 * DN;

        uint32_t* OUT = sel ? KF : QF;
#pragma unroll
        for (int nt = 0; nt < 16; ++nt) {
            int col = nt * 8 + 2 * tig;
            OUT[r0 * 132 + col]     = fbits(RATIO * (expf(acc[nt][0] * DN + c0) + KEPS));
            OUT[r0 * 132 + col + 1] = fbits(RATIO * (expf(acc[nt][1] * DN + c0) + KEPS));
            OUT[r1 * 132 + col]     = fbits(RATIO * (expf(acc[nt][2] * DN + c1) + KEPS));
            OUT[r1 * 132 + col + 1] = fbits(RATIO * (expf(acc[nt][3] * DN + c1) + KEPS));
        }
        __syncthreads();
    }

    // ---- load v -> DB as vT[e][s] (stride 132) ----
    {
        int s = tid >> 1, e0 = (tid & 1) * 32;
        const float* src = g_qkv + (size_t)s * ROW_QKV + base_nh + 2 * MDL + e0;
#pragma unroll
        for (int j = 0; j < 8; ++j) {
            float4 v = *(const float4*)(src + j * 4);
            DB[(e0 + j * 4 + 0) * 132 + s] = fbits(v.x);
            DB[(e0 + j * 4 + 1) * 132 + s] = fbits(v.y);
            DB[(e0 + j * 4 + 2) * 132 + s] = fbits(v.z);
            DB[(e0 + j * 4 + 3) * 132 + s] = fbits(v.w);
        }
    }

    // ---- P = qf @ kf^T ----
    float acc[16][4];
#pragma unroll
    for (int nt = 0; nt < 16; ++nt)
#pragma unroll
        for (int r = 0; r < 4; ++r) acc[nt][r] = 0.f;

    {
        uint32_t aB = s2u(QF) + ((w * 16 * 132) << 2) + a132;
        uint32_t bB = s2u(KF) + b132;
#pragma unroll
        for (int kk = 0; kk < 128; kk += 8) {
            uint32_t a0, a1, a2, a3;
            ldm_x4(a0, a1, a2, a3, aB + (kk << 2));
#pragma unroll
            for (int p = 0; p < 8; ++p) {
                uint32_t b0, b1, b2, b3;
                ldm_x4(b0, b1, b2, b3, bB + ((p * 16 * 132 + kk) << 2));
                MMA_TF32(acc[2 * p],     a0, a1, a2, a3, b0, b1);
                MMA_TF32(acc[2 * p + 1], a0, a1, a2, a3, b2, b3);
            }
        }
    }

    {
        float d0 = 0.f, d1 = 0.f;
#pragma unroll
        for (int nt = 0; nt < 16; ++nt) {
            d0 += acc[nt][0] + acc[nt][1];
            d1 += acc[nt][2] + acc[nt][3];
        }
        d0 += __shfl_xor_sync(0xffffffffu, d0, 1);
        d0 += __shfl_xor_sync(0xffffffffu, d0, 2);
        d1 += __shfl_xor_sync(0xffffffffu, d1, 1);
        d1 += __shfl_xor_sync(0xffffffffu, d1, 2);
        if (tig == 0) { DEN[r0] = d0; DEN[r1] = d1; }
    }
    __syncthreads();

#pragma unroll
    for (int nt = 0; nt < 16; ++nt) {
        int col = nt * 8 + 2 * tig;
        QF[r0 * 132 + col]     = fbits(acc[nt][0]);
        QF[r0 * 132 + col + 1] = fbits(acc[nt][1]);
        QF[r1 * 132 + col]     = fbits(acc[nt][2]);
        QF[r1 * 132 + col + 1] = fbits(acc[nt][3]);
    }
    __syncthreads();

    // ---- t = (P @ v) / den ----
    float acc3[8][4];
#pragma unroll
    for (int nt = 0; nt < 8; ++nt)
#pragma unroll
        for (int r = 0; r < 4; ++r) acc3[nt][r] = 0.f;

    {
        uint32_t aB = s2u(QF) + ((w * 16 * 132) << 2) + a132;
        uint32_t bB = s2u(DB) + b132;
#pragma unroll
        for (int kk = 0; kk < 128; kk += 8) {
            uint32_t a0, a1, a2, a3;
            ldm_x4(a0, a1, a2, a3, aB + (kk << 2));
#pragma unroll
            for (int p = 0; p < 4; ++p) {
                uint32_t b0, b1, b2, b3;
                ldm_x4(b0, b1, b2, b3, bB + ((p * 16 * 132 + kk) << 2));
                MMA_TF32(acc3[2 * p],     a0, a1, a2, a3, b0, b1);
                MMA_TF32(acc3[2 * p + 1], a0, a1, a2, a3, b2, b3);
            }
        }
    }

    const float inv0 = 1.0f / (DEN[r0] + ZEPS);
    const float inv1 = 1.0f / (DEN[r1] + ZEPS);
#pragma unroll
    for (int nt = 0; nt < 8; ++nt) {
        int col = nt * 8 + 2 * tig;
        *(float2*)&g_t[((size_t)r0 * Ndim + n) * MDL + h * Edim + col] =
            make_float2(acc3[nt][0] * inv0, acc3[nt][1] * inv0);
        *(float2*)&g_t[((size_t)r1 * Ndim + n) * MDL + h * Edim + col] =
            make_float2(acc3[nt][2] * inv1, acc3[nt][3] * inv1);
    }
}

// ---------------------------------------------------------------------------
// AddNorm
// ---------------------------------------------------------------------------
__global__ void __launch_bounds__(128) addnorm_k(
    const float* __restrict__ a, const float* __restrict__ res,
    const float* __restrict__ g, const float* __restrict__ b,
    float* __restrict__ out)
{
    __shared__ float red[8];
    const int r = blockIdx.x, tid = threadIdx.x;
    const size_t base = (size_t)r * MDL + tid * 4;

    float4 va = *(const float4*)(a + base);
    float4 vr = *(const float4*)(res + base);
    float v[4] = { va.x + vr.x, va.y + vr.y, va.z + vr.z, va.w + vr.w };

    float s  = v[0] + v[1] + v[2] + v[3];
    float s2 = v[0]*v[0] + v[1]*v[1] + v[2]*v[2] + v[3]*v[3];
#pragma unroll
    for (int o = 16; o > 0; o >>= 1) {
        s  += __shfl_xor_sync(0xffffffffu, s,  o);
        s2 += __shfl_xor_sync(0xffffffffu, s2, o);
    }
    if ((tid & 31) == 0) { red[tid >> 5] = s; red[4 + (tid >> 5)] = s2; }
    __syncthreads();
    float ts  = red[0] + red[1] + red[2] + red[3];
    float ts2 = red[4] + red[5] + red[6] + red[7];
    float mean = ts * (1.0f / MDL);
    float var  = ts2 * (1.0f / MDL) - mean * mean;
    float rstd = rsqrtf(var + LNEPS);

    float4 gg = *(const float4*)(g + tid * 4);
    float4 bb = *(const float4*)(b + tid * 4);
    float4 o;
    o.x = (v[0] - mean) * rstd * gg.x + bb.x;
    o.y = (v[1] - mean) * rstd * gg.y + bb.y;
    o.z = (v[2] - mean) * rstd * gg.z + bb.z;
    o.w = (v[3] - mean) * rstd * gg.w + bb.w;
    *(float4*)(out + base) = o;
}

// ---------------------------------------------------------------------------
// Host launcher
// ---------------------------------------------------------------------------
extern "C" void kernel_launch(void* const* d_in, const int* in_sizes, int n_in,
                              void* d_out, int out_size)
{
    const float* x     = (const float*)d_in[0];
    const float* w_qkv = (const float*)d_in[1];
    const float* b_qkv = (const float*)d_in[2];
    const float* proj  = (const float*)d_in[3];
    const float* ln1_g = (const float*)d_in[4];
    const float* ln1_b = (const float*)d_in[5];
    const float* ln2_g = (const float*)d_in[6];
    const float* ln2_b = (const float*)d_in[7];
    const float* w1    = (const float*)d_in[8];
    const float* b1    = (const float*)d_in[9];
    const float* w2    = (const float*)d_in[10];
    const float* b2    = (const float*)d_in[11];
    float* out = (float*)d_out;

    float *p_qkv, *p_t, *p_x1, *p_h1, *p_y;
    cudaGetSymbolAddress((void**)&p_qkv, g_qkv);
    cudaGetSymbolAddress((void**)&p_t,   g_t);
    cudaGetSymbolAddress((void**)&p_x1,  g_x1);
    cudaGetSymbolAddress((void**)&p_h1,  g_h1);
    cudaGetSymbolAddress((void**)&p_y,   g_y);

    const int gemm_smem  = 18432 * 4;    // 73728 B
    const int fused_smem = 51456 * 4;    // 205824 B
    cudaFuncSetAttribute(tf32gemm, cudaFuncAttributeMaxDynamicSharedMemorySize,
                         gemm_smem);
    cudaFuncSetAttribute(fused_attn, cudaFuncAttributeMaxDynamicSharedMemorySize,
                         fused_smem);

    // 1) qkv = x @ w_qkv^T + b_qkv   [65536, 1536]
    tf32gemm<<<dim3(QKV_STRIDE / 128, ROWS / 128), 256, gemm_smem>>>(
        x, w_qkv, b_qkv, p_qkv, ROWS, QKV_STRIDE, MDL, 0);

    // 2) fused FAVOR+ attention -> g_t
    fused_attn<<<Ndim * HEADS, 256, fused_smem>>>(proj);

    // 3) x1 = LN(t + x)
    addnorm_k<<<ROWS, 128>>>(p_t, x, ln1_g, ln1_b, p_x1);

    // 4) h1 = gelu(x1 @ w1^T + b1)   [65536, 256]
    tf32gemm<<<dim3(HID / 128, ROWS / 128), 256, gemm_smem>>>(
        p_x1, w1, b1, p_h1, ROWS, HID, MDL, 1);

    // 5) y = h1 @ w2^T + b2          [65536, 512]
    tf32gemm<<<dim3(MDL / 128, ROWS / 128), 256, gemm_smem>>>(
        p_h1, w2, b2, p_y, ROWS, MDL, HID, 0);

    // 6) out = LN(y + x1)
    addnorm_k<<<ROWS, 128>>>(p_y, p_x1, ln2_g, ln2_b, out);
}